// round 1
// baseline (speedup 1.0000x reference)
#include <cuda_runtime.h>

#define NN   100000
#define EE   1600000
#define TW   12
#define CI_N 16
#define CMID 32
#define COUT 32

// ---- scratch (allocation-free rule: __device__ globals) ----
__device__ float g_deg[NN];
__device__ float g_dis[NN];
__device__ int   g_cnt[NN];
__device__ int   g_off[NN + 1];
__device__ int   g_cur[NN];
__device__ int   g_src[EE];
__device__ float g_nrm[EE];
__device__ float g_h  [(size_t)TW * NN * CMID];   // 153.6 MB
__device__ float g_agg[(size_t)TW * NN * CMID];   // 153.6 MB

// ---------- 0: zero accumulators ----------
__global__ void k_zero() {
    int i = blockIdx.x * blockDim.x + threadIdx.x;
    if (i < NN) { g_deg[i] = 0.f; g_cnt[i] = 0; }
}

// ---------- 1: weighted degree + edge-count histogram over dst ----------
__global__ void k_deg(const int* __restrict__ A, const float* __restrict__ ew) {
    int e = blockIdx.x * blockDim.x + threadIdx.x;
    if (e < EE) {
        int c = A[EE + e];                 // dst
        atomicAdd(&g_deg[c], ew[e]);
        atomicAdd(&g_cnt[c], 1);
    }
}

// ---------- 2: dis = deg>0 ? rsqrt(deg) : 0 ----------
__global__ void k_dis() {
    int i = blockIdx.x * blockDim.x + threadIdx.x;
    if (i < NN) { float d = g_deg[i]; g_dis[i] = d > 0.f ? rsqrtf(d) : 0.f; }
}

// ---------- 3: exclusive scan of g_cnt -> g_off, init cursors ----------
__global__ void k_scan() {
    __shared__ int wsum[33];
    const int tid = threadIdx.x, lane = tid & 31, wid = tid >> 5;
    int carry = 0;
    const int nchunk = (NN + 1023) / 1024;
    for (int ch = 0; ch < nchunk; ch++) {
        int i = ch * 1024 + tid;
        int v = (i < NN) ? g_cnt[i] : 0;
        int incl = v;
        #pragma unroll
        for (int d = 1; d < 32; d <<= 1) {
            int t = __shfl_up_sync(0xffffffffu, incl, d);
            if (lane >= d) incl += t;
        }
        if (lane == 31) wsum[wid] = incl;
        __syncthreads();
        if (wid == 0) {
            int x  = wsum[lane];
            int ix = x;
            #pragma unroll
            for (int d = 1; d < 32; d <<= 1) {
                int t = __shfl_up_sync(0xffffffffu, ix, d);
                if (lane >= d) ix += t;
            }
            wsum[lane] = ix - x;            // exclusive warp offsets
            if (lane == 31) wsum[32] = ix;  // block total
        }
        __syncthreads();
        int excl = carry + wsum[wid] + incl - v;
        if (i < NN) { g_off[i] = excl; g_cur[i] = excl; }
        carry += wsum[32];
        __syncthreads();
    }
    if (tid == 0) g_off[NN] = carry;   // == EE
}

// ---------- 4: scatter edges into dst-sorted CSR, fuse norm ----------
__global__ void k_scatter(const int* __restrict__ A, const float* __restrict__ ew) {
    int e = blockIdx.x * blockDim.x + threadIdx.x;
    if (e < EE) {
        int r = A[e], c = A[EE + e];
        int idx = atomicAdd(&g_cur[c], 1);
        g_src[idx] = r;
        g_nrm[idx] = g_dis[r] * ew[e] * g_dis[c];
    }
}

// ---------- 5: h[t] = x[t] @ gcn_w[t]  (warp per node, lane = out channel) ----------
__global__ void k_gcn(const float* __restrict__ x, const float* __restrict__ gw) {
    __shared__ float ws[CI_N * CMID];              // 512 floats
    const int t = blockIdx.y;
    const int tid = threadIdx.x;
    for (int i = tid; i < CI_N * CMID; i += 256) ws[i] = gw[t * CI_N * CMID + i];
    __syncthreads();
    const int lane = tid & 31, wid = tid >> 5;
    const int n = blockIdx.x * 8 + wid;            // 12500*8 == NN exactly
    float xr = 0.f;
    if (lane < CI_N) xr = x[((size_t)t * NN + n) * CI_N + lane];
    float acc = 0.f;
    #pragma unroll
    for (int ci = 0; ci < CI_N; ci++) {
        float xv = __shfl_sync(0xffffffffu, xr, ci);
        acc = fmaf(xv, ws[ci * CMID + lane], acc);
    }
    g_h[((size_t)t * NN + n) * CMID + lane] = acc;
}

// ---------- 6: CSR aggregation, zero atomics (warp per (t,dst), lane = channel) ----------
__global__ void k_agg(const float* __restrict__ gb) {
    const int t = blockIdx.y;
    const int lane = threadIdx.x & 31, wid = threadIdx.x >> 5;
    const int dst = blockIdx.x * 8 + wid;
    float acc = gb[t * CMID + lane];
    const int e0 = g_off[dst], e1 = g_off[dst + 1];
    const float* __restrict__ hb = g_h + (size_t)t * NN * CMID;
    int e = e0;
    for (; e + 1 < e1; e += 2) {
        int   s0 = g_src[e],   s1 = g_src[e + 1];
        float w0 = g_nrm[e],   w1 = g_nrm[e + 1];
        float v0 = hb[(size_t)s0 * CMID + lane];
        float v1 = hb[(size_t)s1 * CMID + lane];
        acc = fmaf(w0, v0, acc);
        acc = fmaf(w1, v1, acc);
    }
    if (e < e1) {
        int s = g_src[e];
        acc = fmaf(g_nrm[e], hb[(size_t)s * CMID + lane], acc);
    }
    g_agg[((size_t)t * NN + dst) * CMID + lane] = acc;
}

// ---------- 7: temporal Conv1d(K=3,'same') + bias + LeakyReLU ----------
// block (32,4): tx = out channel, ty = local node; 4 nodes/block
__global__ void k_conv(const float* __restrict__ cw, const float* __restrict__ cb,
                       float* __restrict__ out) {
    __shared__ float sh[4][TW + 2][CMID];          // padded time axis, 7 KB
    __shared__ float cwsh[CMID * 3 * COUT];        // 12 KB, [(ci*3+k)*32 + co]
    const int tid = threadIdx.y * 32 + threadIdx.x;

    for (int i = tid; i < COUT * CMID * 3; i += 128) {
        int co = i / (CMID * 3);
        int r  = i - co * (CMID * 3);              // ci*3+k
        cwsh[r * COUT + co] = cw[i];
    }
    for (int i = tid; i < 4 * CMID; i += 128) {
        int nl = i >> 5, c = i & 31;
        sh[nl][0][c]      = 0.f;
        sh[nl][TW + 1][c] = 0.f;
    }
    const int node0 = blockIdx.x * 4;              // 25000*4 == NN exactly
    {
        const int nl = threadIdx.y, c = threadIdx.x;
        #pragma unroll
        for (int t = 0; t < TW; t++)
            sh[nl][t + 1][c] = g_agg[((size_t)t * NN + node0 + nl) * CMID + c];
    }
    __syncthreads();

    const int co = threadIdx.x, nl = threadIdx.y;
    const float bias = cb[co];
    float acc[TW];
    #pragma unroll
    for (int w = 0; w < TW; w++) acc[w] = bias;

    #pragma unroll
    for (int ci = 0; ci < CMID; ci++) {
        float w0 = cwsh[(ci * 3 + 0) * COUT + co];
        float w1 = cwsh[(ci * 3 + 1) * COUT + co];
        float w2 = cwsh[(ci * 3 + 2) * COUT + co];
        float vp = sh[nl][0][ci];
        float vc = sh[nl][1][ci];
        #pragma unroll
        for (int w = 0; w < TW; w++) {
            float vn = sh[nl][w + 2][ci];
            acc[w] = fmaf(w0, vp, acc[w]);
            acc[w] = fmaf(w1, vc, acc[w]);
            acc[w] = fmaf(w2, vn, acc[w]);
            vp = vc; vc = vn;
        }
    }

    const size_t base = ((size_t)(node0 + nl) * TW) * COUT + co;
    #pragma unroll
    for (int w = 0; w < TW; w++) {
        float v = acc[w];
        v = v >= 0.f ? v : 0.01f * v;
        out[base + (size_t)w * COUT] = v;
    }
}

extern "C" void kernel_launch(void* const* d_in, const int* in_sizes, int n_in,
                              void* d_out, int out_size) {
    const float* x  = (const float*)d_in[0];   // [W,N,16]
    const int*   A  = (const int*)  d_in[1];   // [2,E]
    const float* ew = (const float*)d_in[2];   // [E]
    const float* gw = (const float*)d_in[3];   // [W,16,32]
    const float* gb = (const float*)d_in[4];   // [W,32]
    const float* cw = (const float*)d_in[5];   // [32,32,3]
    const float* cb = (const float*)d_in[6];   // [32]
    float* out = (float*)d_out;                // [N,W,32]

    k_zero   <<<(NN + 255) / 256, 256>>>();
    k_deg    <<<(EE + 255) / 256, 256>>>(A, ew);
    k_dis    <<<(NN + 255) / 256, 256>>>();
    k_scan   <<<1, 1024>>>();
    k_scatter<<<(EE + 255) / 256, 256>>>(A, ew);

    dim3 gg(NN / 8, TW);
    k_gcn<<<gg, 256>>>(x, gw);
    k_agg<<<gg, 256>>>(gb);

    k_conv<<<NN / 4, dim3(32, 4)>>>(cw, cb, out);
}

// round 2
// speedup vs baseline: 1.4362x; 1.4362x over previous
#include <cuda_runtime.h>

#define NN   100000
#define EE   1600000
#define TW   12
#define CI_N 16
#define CMID 32
#define COUT 32

#define SCAN_BLK 1024
#define NSCAN_BLKS ((NN + SCAN_BLK - 1) / SCAN_BLK)   // 98

// ---- scratch (allocation-free rule: __device__ globals) ----
__device__ float g_deg[NN];
__device__ float g_dis[NN];
__device__ int   g_cnt[NN];
__device__ int   g_off[NN + 1];
__device__ int   g_cur[NN];
__device__ int   g_bsum[NSCAN_BLKS];
__device__ int   g_boff[NSCAN_BLKS];
__device__ int   g_src[EE];
__device__ float g_nrm[EE];
__device__ float g_ax [(size_t)TW * NN * CI_N];   // aggregated x, 76.8 MB

// ---------- 0: zero accumulators ----------
__global__ void k_zero() {
    int i = blockIdx.x * blockDim.x + threadIdx.x;
    if (i < NN) { g_deg[i] = 0.f; g_cnt[i] = 0; }
}

// ---------- 1: weighted degree + edge-count histogram over dst ----------
__global__ void k_deg(const int* __restrict__ A, const float* __restrict__ ew) {
    int e = blockIdx.x * blockDim.x + threadIdx.x;
    if (e < EE) {
        int c = A[EE + e];                 // dst
        atomicAdd(&g_deg[c], ew[e]);
        atomicAdd(&g_cnt[c], 1);
    }
}

// ---------- 2: dis = deg>0 ? rsqrt(deg) : 0 ----------
__global__ void k_dis() {
    int i = blockIdx.x * blockDim.x + threadIdx.x;
    if (i < NN) { float d = g_deg[i]; g_dis[i] = d > 0.f ? rsqrtf(d) : 0.f; }
}

// ---------- 3a: per-block exclusive scan of g_cnt; block totals -> g_bsum ----------
__global__ void k_scan1() {
    __shared__ int wsum[33];
    const int tid = threadIdx.x, lane = tid & 31, wid = tid >> 5;
    const int i = blockIdx.x * SCAN_BLK + tid;
    int v = (i < NN) ? g_cnt[i] : 0;
    int incl = v;
    #pragma unroll
    for (int d = 1; d < 32; d <<= 1) {
        int t = __shfl_up_sync(0xffffffffu, incl, d);
        if (lane >= d) incl += t;
    }
    if (lane == 31) wsum[wid] = incl;
    __syncthreads();
    if (wid == 0) {
        int x  = wsum[lane];
        int ix = x;
        #pragma unroll
        for (int d = 1; d < 32; d <<= 1) {
            int t = __shfl_up_sync(0xffffffffu, ix, d);
            if (lane >= d) ix += t;
        }
        wsum[lane] = ix - x;
        if (lane == 31) wsum[32] = ix;
    }
    __syncthreads();
    if (i < NN) g_off[i] = wsum[wid] + incl - v;   // block-local exclusive
    if (tid == 0) g_bsum[blockIdx.x] = wsum[32];
}

// ---------- 3b: exclusive scan of the 98 block totals ----------
__global__ void k_scan2() {
    const int lane = threadIdx.x & 31, wid = threadIdx.x >> 5;
    __shared__ int wtot[4];
    int v = (threadIdx.x < NSCAN_BLKS) ? g_bsum[threadIdx.x] : 0;
    int incl = v;
    #pragma unroll
    for (int d = 1; d < 32; d <<= 1) {
        int t = __shfl_up_sync(0xffffffffu, incl, d);
        if (lane >= d) incl += t;
    }
    if (lane == 31) wtot[wid] = incl;
    __syncthreads();
    int base = 0;
    for (int w = 0; w < wid; w++) base += wtot[w];
    if (threadIdx.x < NSCAN_BLKS) g_boff[threadIdx.x] = base + incl - v;
}

// ---------- 3c: add block offsets, init cursors, sentinel ----------
__global__ void k_scan3() {
    int i = blockIdx.x * blockDim.x + threadIdx.x;
    if (i < NN) {
        int o = g_off[i] + g_boff[blockIdx.x * SCAN_BLK >= 0 ? (i / SCAN_BLK) : 0];
        g_off[i] = o;
        g_cur[i] = o;
    }
    if (i == 0) g_off[NN] = EE;
}

// ---------- 4: scatter edges into dst-sorted CSR, fuse norm ----------
__global__ void k_scatter(const int* __restrict__ A, const float* __restrict__ ew) {
    int e = blockIdx.x * blockDim.x + threadIdx.x;
    if (e < EE) {
        int r = A[e], c = A[EE + e];
        int idx = atomicAdd(&g_cur[c], 1);
        g_src[idx] = r;
        g_nrm[idx] = g_dis[r] * ew[e] * g_dis[c];
    }
}

// ---------- 5: aggregate x directly (linearity: segsum(norm*x[src]) @ W == agg) ----------
// warp per (t, dst); lanes 0-15 handle even edges, 16-31 odd edges; ch = lane&15
__global__ void k_aggx(const float* __restrict__ x) {
    const int t    = blockIdx.y;
    const int lane = threadIdx.x & 31, wid = threadIdx.x >> 5;
    const int dst  = blockIdx.x * 8 + wid;          // 12500*8 == NN
    const int half = lane >> 4, ch = lane & 15;
    const int e0 = g_off[dst], e1 = g_off[dst + 1];
    const float* __restrict__ xb = x + (size_t)t * NN * CI_N;
    float acc0 = 0.f, acc1 = 0.f;
    int e = e0 + half;
    // 2-deep unroll per half-warp: 4 edges in flight per warp iteration
    for (; e + 2 < e1; e += 4) {
        int   s0 = g_src[e],     s1 = g_src[e + 2];
        float w0 = g_nrm[e],     w1 = g_nrm[e + 2];
        float v0 = xb[(size_t)s0 * CI_N + ch];
        float v1 = xb[(size_t)s1 * CI_N + ch];
        acc0 = fmaf(w0, v0, acc0);
        acc1 = fmaf(w1, v1, acc1);
    }
    for (; e < e1; e += 2) {
        int s = g_src[e];
        acc0 = fmaf(g_nrm[e], xb[(size_t)s * CI_N + ch], acc0);
    }
    float acc = acc0 + acc1;
    acc += __shfl_xor_sync(0xffffffffu, acc, 16);
    if (half == 0)
        g_ax[((size_t)t * NN + dst) * CI_N + ch] = acc;
}

// ---------- 6: fused GCN-GEMM (16->32, +bias) + temporal Conv1d(K=3) + LeakyReLU ----------
// block (32,16): tx = out channel, ty = local node; 16 nodes/block, 6250 blocks
#define NPB 16
__global__ __launch_bounds__(512, 2)
void k_conv(const float* __restrict__ gw, const float* __restrict__ gb,
            const float* __restrict__ cw, const float* __restrict__ cb,
            float* __restrict__ out) {
    __shared__ float gws[TW * CI_N * CMID];        // 24 KB  [t*512 + ci*32 + co]
    __shared__ float gbs[TW * CMID];               // 1.5 KB
    __shared__ float cws[CMID * 3 * COUT];         // 12 KB  [(ci*3+k)*32 + co]
    __shared__ float axs[NPB][TW][CI_N];           // 12 KB
    __shared__ float sh [NPB][TW + 2][CMID];       // 28 KB  padded time axis
    const int tid = threadIdx.y * 32 + threadIdx.x;
    const int node0 = blockIdx.x * NPB;

    for (int i = tid; i < TW * CI_N * CMID; i += 512) gws[i] = gw[i];
    for (int i = tid; i < TW * CMID;        i += 512) gbs[i] = gb[i];
    for (int i = tid; i < COUT * CMID * 3;  i += 512) {
        int co = i / (CMID * 3);
        int r  = i - co * (CMID * 3);
        cws[r * COUT + co] = cw[i];
    }
    // load aggregated x tile: per t, 16 nodes * 16 ch = 256 contiguous floats
    for (int i = tid; i < NPB * TW * CI_N; i += 512) {
        int t  = i / (NPB * CI_N);
        int r  = i - t * (NPB * CI_N);
        int nl = r >> 4, ch = r & 15;
        axs[nl][t][ch] = g_ax[((size_t)t * NN + node0 + nl) * CI_N + ch];
    }
    // zero time-axis pads
    for (int i = tid; i < NPB * CMID; i += 512) {
        int nl = i >> 5, c = i & 31;
        sh[nl][0][c]      = 0.f;
        sh[nl][TW + 1][c] = 0.f;
    }
    __syncthreads();

    const int co = threadIdx.x, nl = threadIdx.y;
    // GCN GEMM: h[nl][t][co] = sum_ci axs[nl][t][ci] * W[t][ci][co] + b[t][co]
    #pragma unroll
    for (int t = 0; t < TW; t++) {
        float acc = gbs[t * CMID + co];
        #pragma unroll
        for (int ci = 0; ci < CI_N; ci++)
            acc = fmaf(axs[nl][t][ci], gws[t * 512 + ci * 32 + co], acc);
        sh[nl][t + 1][co] = acc;
    }
    __syncthreads();

    // temporal conv over the smem slab
    const float bias = cb[co];
    float acc[TW];
    #pragma unroll
    for (int w = 0; w < TW; w++) acc[w] = bias;
    #pragma unroll
    for (int ci = 0; ci < CMID; ci++) {
        float w0 = cws[(ci * 3 + 0) * COUT + co];
        float w1 = cws[(ci * 3 + 1) * COUT + co];
        float w2 = cws[(ci * 3 + 2) * COUT + co];
        float vp = sh[nl][0][ci];
        float vc = sh[nl][1][ci];
        #pragma unroll
        for (int w = 0; w < TW; w++) {
            float vn = sh[nl][w + 2][ci];
            acc[w] = fmaf(w0, vp, acc[w]);
            acc[w] = fmaf(w1, vc, acc[w]);
            acc[w] = fmaf(w2, vn, acc[w]);
            vp = vc; vc = vn;
        }
    }

    const size_t base = ((size_t)(node0 + nl) * TW) * COUT + co;
    #pragma unroll
    for (int w = 0; w < TW; w++) {
        float v = acc[w];
        v = v >= 0.f ? v : 0.01f * v;
        out[base + (size_t)w * COUT] = v;
    }
}

extern "C" void kernel_launch(void* const* d_in, const int* in_sizes, int n_in,
                              void* d_out, int out_size) {
    const float* x  = (const float*)d_in[0];   // [W,N,16]
    const int*   A  = (const int*)  d_in[1];   // [2,E]
    const float* ew = (const float*)d_in[2];   // [E]
    const float* gw = (const float*)d_in[3];   // [W,16,32]
    const float* gb = (const float*)d_in[4];   // [W,32]
    const float* cw = (const float*)d_in[5];   // [32,32,3]
    const float* cb = (const float*)d_in[6];   // [32]
    float* out = (float*)d_out;                // [N,W,32]

    k_zero   <<<(NN + 255) / 256, 256>>>();
    k_deg    <<<(EE + 255) / 256, 256>>>(A, ew);
    k_dis    <<<(NN + 255) / 256, 256>>>();
    k_scan1  <<<NSCAN_BLKS, SCAN_BLK>>>();
    k_scan2  <<<1, 128>>>();
    k_scan3  <<<NSCAN_BLKS, SCAN_BLK>>>();
    k_scatter<<<(EE + 255) / 256, 256>>>(A, ew);

    k_aggx<<<dim3(NN / 8, TW), 256>>>(x);
    k_conv<<<NN / NPB, dim3(32, NPB)>>>(gw, gb, cw, cb, out);
}

// round 3
// speedup vs baseline: 2.8645x; 1.9945x over previous
#include <cuda_runtime.h>

#define NN   100000
#define EE   1600000
#define TW   12
#define CI_N 16
#define CMID 32
#define COUT 32

#define SCAN_BLK 1024
#define NSCAN_BLKS ((NN + SCAN_BLK - 1) / SCAN_BLK)   // 98

// ---- scratch (allocation-free rule: __device__ globals) ----
__device__ float  g_deg[NN];
__device__ float  g_dis[NN];
__device__ int    g_cnt[NN];
__device__ int    g_off[NN + 1];
__device__ int    g_cur[NN];
__device__ int    g_bsum[NSCAN_BLKS];
__device__ int    g_boff[NSCAN_BLKS];
__device__ float2 g_edge[EE];                       // (src as int bits, norm)
__device__ float  g_xs[(size_t)NN * TW * CI_N];     // x transposed node-major, 76.8 MB
__device__ float  g_ax[(size_t)NN * TW * CI_N];     // aggregated x, node-major, 76.8 MB
__device__ float  g_M [TW * 3 * CI_N * COUT];       // fused gcn_w @ conv_w, 73.7 KB
__device__ float  g_B [TW * COUT];                  // fused bias

// ---------- 0: zero accumulators ----------
__global__ void k_zero() {
    int i = blockIdx.x * blockDim.x + threadIdx.x;
    if (i < NN) { g_deg[i] = 0.f; g_cnt[i] = 0; }
}

// ---------- 1: weighted degree + edge-count histogram over dst ----------
__global__ void k_deg(const int* __restrict__ A, const float* __restrict__ ew) {
    int e = blockIdx.x * blockDim.x + threadIdx.x;
    if (e < EE) {
        int c = A[EE + e];
        atomicAdd(&g_deg[c], ew[e]);
        atomicAdd(&g_cnt[c], 1);
    }
}

// ---------- 2: dis = deg>0 ? rsqrt(deg) : 0 ----------
__global__ void k_dis() {
    int i = blockIdx.x * blockDim.x + threadIdx.x;
    if (i < NN) { float d = g_deg[i]; g_dis[i] = d > 0.f ? rsqrtf(d) : 0.f; }
}

// ---------- 3a: per-block exclusive scan of g_cnt ----------
__global__ void k_scan1() {
    __shared__ int wsum[33];
    const int tid = threadIdx.x, lane = tid & 31, wid = tid >> 5;
    const int i = blockIdx.x * SCAN_BLK + tid;
    int v = (i < NN) ? g_cnt[i] : 0;
    int incl = v;
    #pragma unroll
    for (int d = 1; d < 32; d <<= 1) {
        int t = __shfl_up_sync(0xffffffffu, incl, d);
        if (lane >= d) incl += t;
    }
    if (lane == 31) wsum[wid] = incl;
    __syncthreads();
    if (wid == 0) {
        int x  = wsum[lane];
        int ix = x;
        #pragma unroll
        for (int d = 1; d < 32; d <<= 1) {
            int t = __shfl_up_sync(0xffffffffu, ix, d);
            if (lane >= d) ix += t;
        }
        wsum[lane] = ix - x;
        if (lane == 31) wsum[32] = ix;
    }
    __syncthreads();
    if (i < NN) g_off[i] = wsum[wid] + incl - v;
    if (tid == 0) g_bsum[blockIdx.x] = wsum[32];
}

// ---------- 3b: exclusive scan of block totals ----------
__global__ void k_scan2() {
    const int lane = threadIdx.x & 31, wid = threadIdx.x >> 5;
    __shared__ int wtot[4];
    int v = (threadIdx.x < NSCAN_BLKS) ? g_bsum[threadIdx.x] : 0;
    int incl = v;
    #pragma unroll
    for (int d = 1; d < 32; d <<= 1) {
        int t = __shfl_up_sync(0xffffffffu, incl, d);
        if (lane >= d) incl += t;
    }
    if (lane == 31) wtot[wid] = incl;
    __syncthreads();
    int base = 0;
    for (int w = 0; w < wid; w++) base += wtot[w];
    if (threadIdx.x < NSCAN_BLKS) g_boff[threadIdx.x] = base + incl - v;
}

// ---------- 3c: add block offsets, init cursors ----------
__global__ void k_scan3() {
    int i = blockIdx.x * blockDim.x + threadIdx.x;
    if (i < NN) {
        int o = g_off[i] + g_boff[i / SCAN_BLK];
        g_off[i] = o;
        g_cur[i] = o;
    }
    if (i == 0) g_off[NN] = EE;
}

// ---------- 4: scatter edges into dst-sorted CSR (packed src+norm) ----------
__global__ void k_scatter(const int* __restrict__ A, const float* __restrict__ ew) {
    int e = blockIdx.x * blockDim.x + threadIdx.x;
    if (e < EE) {
        int r = A[e], c = A[EE + e];
        int idx = atomicAdd(&g_cur[c], 1);
        float nrm = g_dis[r] * ew[e] * g_dis[c];
        g_edge[idx] = make_float2(__int_as_float(r), nrm);
    }
}

// ---------- 5: transpose x -> node-major xs[n][t][ch] ----------
__global__ void k_xs(const float* __restrict__ x) {
    // 19.2M elements, 4 per thread, coalesced float4 writes
    size_t j0 = ((size_t)blockIdx.x * blockDim.x + threadIdx.x) * 4;
    float4 v;
    {
        size_t j = j0;
        int n = (int)(j / 192), rem = (int)(j % 192);
        int t = rem >> 4, ch = rem & 15;
        v.x = x[((size_t)t * NN + n) * 16 + ch];
        j = j0 + 1; n = (int)(j / 192); rem = (int)(j % 192); t = rem >> 4; ch = rem & 15;
        v.y = x[((size_t)t * NN + n) * 16 + ch];
        j = j0 + 2; n = (int)(j / 192); rem = (int)(j % 192); t = rem >> 4; ch = rem & 15;
        v.z = x[((size_t)t * NN + n) * 16 + ch];
        j = j0 + 3; n = (int)(j / 192); rem = (int)(j % 192); t = rem >> 4; ch = rem & 15;
        v.w = x[((size_t)t * NN + n) * 16 + ch];
    }
    *(float4*)(g_xs + j0) = v;
}

// ---------- 6: fuse weights: M[t][k][ci][co] = sum_cm gw[t][ci][cm]*cw[co][cm][k] ----------
__global__ void k_fuse(const float* __restrict__ gw, const float* __restrict__ cw) {
    const int b = blockIdx.x;          // 0..35
    const int t = b / 3, k = b % 3;
    const int co = threadIdx.x, ci = threadIdx.y;
    float acc = 0.f;
    #pragma unroll
    for (int cm = 0; cm < CMID; cm++)
        acc = fmaf(gw[(t * CI_N + ci) * CMID + cm], cw[(co * CMID + cm) * 3 + k], acc);
    g_M[((t * 3 + k) * CI_N + ci) * COUT + co] = acc;
}

// ---------- 6b: fused bias B[w][co] ----------
__global__ void k_bias(const float* __restrict__ gb, const float* __restrict__ cw,
                       const float* __restrict__ cb) {
    const int co = threadIdx.x, w = threadIdx.y;
    float acc = cb[co];
    #pragma unroll
    for (int k = 0; k < 3; k++) {
        int t = w + k - 1;
        if (t >= 0 && t < TW)
            #pragma unroll
            for (int cm = 0; cm < CMID; cm++)
                acc = fmaf(gb[t * CMID + cm], cw[(co * CMID + cm) * 3 + k], acc);
    }
    g_B[w * COUT + co] = acc;
}

// ---------- 7: single-pass all-t aggregation (warp per dst, zero atomics) ----------
__global__ void k_agg() {
    const int lane = threadIdx.x & 31, wid = threadIdx.x >> 5;
    const int dst = blockIdx.x * 8 + wid;              // 12500*8 == NN
    const int e0 = g_off[dst], e1 = g_off[dst + 1];
    float2 a0 = {0.f, 0.f}, a1 = {0.f, 0.f}, a2 = {0.f, 0.f};
    #pragma unroll 2
    for (int e = e0; e < e1; e++) {
        float2 ed = g_edge[e];                         // broadcast
        int   s = __float_as_int(ed.x);
        float w = ed.y;
        const float2* p = (const float2*)(g_xs + (size_t)s * 192) + lane;
        float2 v0 = p[0], v1 = p[32], v2 = p[64];
        a0.x = fmaf(w, v0.x, a0.x); a0.y = fmaf(w, v0.y, a0.y);
        a1.x = fmaf(w, v1.x, a1.x); a1.y = fmaf(w, v1.y, a1.y);
        a2.x = fmaf(w, v2.x, a2.x); a2.y = fmaf(w, v2.y, a2.y);
    }
    float2* q = (float2*)(g_ax + (size_t)dst * 192) + lane;
    q[0] = a0; q[32] = a1; q[64] = a2;
}

// ---------- 8: output GEMM per w: out[n,w,:] = B[w] + sum_r Xs[r]*G_w[r][:] ----------
#define CNODES 128
__global__ __launch_bounds__(256)
void k_out(float* __restrict__ out) {
    __shared__ float Gs[48 * 32];                     // [r][co]
    __shared__ __align__(16) float Xs[48][132];       // [r][node], padded
    __shared__ float Bs[32];
    const int w  = blockIdx.y;
    const int n0 = blockIdx.x * CNODES;
    const int tid = threadIdx.x;

    for (int idx = tid; idx < 48 * 32; idx += 256) {
        int r = idx >> 5, co = idx & 31;
        int k = r >> 4, ci = r & 15;
        int t = w - 1 + k;
        Gs[idx] = (t >= 0 && t < TW) ? g_M[((t * 3 + k) * CI_N + ci) * COUT + co] : 0.f;
    }
    if (tid < 32) Bs[tid] = g_B[w * COUT + tid];
    for (int idx = tid; idx < 48 * CNODES; idx += 256) {
        int nl = idx / 48, r = idx % 48;
        int t  = w - 1 + (r >> 4);
        int n  = n0 + nl;
        float v = 0.f;
        if (t >= 0 && t < TW && n < NN)
            v = g_ax[(size_t)n * 192 + (w - 1) * 16 + r];
        Xs[r][nl] = v;
    }
    __syncthreads();

    const int co2 = tid & 15;          // co pair: {2*co2, 2*co2+1}
    const int ng  = tid >> 4;          // node group: 8 nodes
    float acc[8][2];
    #pragma unroll
    for (int i = 0; i < 8; i++) { acc[i][0] = 0.f; acc[i][1] = 0.f; }

    #pragma unroll
    for (int r = 0; r < 48; r++) {
        float4 va = *(const float4*)&Xs[r][ng * 8];
        float4 vb = *(const float4*)&Xs[r][ng * 8 + 4];
        float2 g  = *(const float2*)&Gs[r * 32 + co2 * 2];
        acc[0][0] = fmaf(va.x, g.x, acc[0][0]); acc[0][1] = fmaf(va.x, g.y, acc[0][1]);
        acc[1][0] = fmaf(va.y, g.x, acc[1][0]); acc[1][1] = fmaf(va.y, g.y, acc[1][1]);
        acc[2][0] = fmaf(va.z, g.x, acc[2][0]); acc[2][1] = fmaf(va.z, g.y, acc[2][1]);
        acc[3][0] = fmaf(va.w, g.x, acc[3][0]); acc[3][1] = fmaf(va.w, g.y, acc[3][1]);
        acc[4][0] = fmaf(vb.x, g.x, acc[4][0]); acc[4][1] = fmaf(vb.x, g.y, acc[4][1]);
        acc[5][0] = fmaf(vb.y, g.x, acc[5][0]); acc[5][1] = fmaf(vb.y, g.y, acc[5][1]);
        acc[6][0] = fmaf(vb.z, g.x, acc[6][0]); acc[6][1] = fmaf(vb.z, g.y, acc[6][1]);
        acc[7][0] = fmaf(vb.w, g.x, acc[7][0]); acc[7][1] = fmaf(vb.w, g.y, acc[7][1]);
    }

    const float b0 = Bs[co2 * 2], b1 = Bs[co2 * 2 + 1];
    #pragma unroll
    for (int i = 0; i < 8; i++) {
        int n = n0 + ng * 8 + i;
        if (n < NN) {
            float v0 = acc[i][0] + b0;
            float v1 = acc[i][1] + b1;
            v0 = v0 >= 0.f ? v0 : 0.01f * v0;
            v1 = v1 >= 0.f ? v1 : 0.01f * v1;
            *(float2*)(out + (size_t)n * (TW * COUT) + w * COUT + co2 * 2)
                = make_float2(v0, v1);
        }
    }
}

extern "C" void kernel_launch(void* const* d_in, const int* in_sizes, int n_in,
                              void* d_out, int out_size) {
    const float* x  = (const float*)d_in[0];   // [W,N,16]
    const int*   A  = (const int*)  d_in[1];   // [2,E]
    const float* ew = (const float*)d_in[2];   // [E]
    const float* gw = (const float*)d_in[3];   // [W,16,32]
    const float* gb = (const float*)d_in[4];   // [W,32]
    const float* cw = (const float*)d_in[5];   // [32,32,3]
    const float* cb = (const float*)d_in[6];   // [32]
    float* out = (float*)d_out;                // [N,W,32]

    k_zero   <<<(NN + 255) / 256, 256>>>();
    k_deg    <<<(EE + 255) / 256, 256>>>(A, ew);
    k_dis    <<<(NN + 255) / 256, 256>>>();
    k_scan1  <<<NSCAN_BLKS, SCAN_BLK>>>();
    k_scan2  <<<1, 128>>>();
    k_scan3  <<<NSCAN_BLKS, SCAN_BLK>>>();
    k_scatter<<<(EE + 255) / 256, 256>>>(A, ew);

    k_xs   <<<(NN * TW * CI_N) / (256 * 4), 256>>>(x);
    k_fuse <<<TW * 3, dim3(COUT, CI_N)>>>(gw, cw);
    k_bias <<<1, dim3(COUT, TW)>>>(gb, cw, cb);

    k_agg<<<NN / 8, 256>>>();
    k_out<<<dim3((NN + CNODES - 1) / CNODES, TW), 256>>>(out);
}

// round 5
// speedup vs baseline: 3.1779x; 1.1094x over previous
#include <cuda_runtime.h>
#include <cuda_fp16.h>

#define NN   100000
#define EE   1600000
#define TW   12
#define CI_N 16
#define CMID 32
#define COUT 32

#define SCAN_BLK 1024
#define NSCAN_BLKS ((NN + SCAN_BLK - 1) / SCAN_BLK)   // 98

// ---- scratch (allocation-free rule: __device__ globals) ----
__device__ float  g_deg[NN];
__device__ float  g_dis[NN];
__device__ int    g_cnt[NN];
__device__ int    g_off[NN + 1];
__device__ int    g_cur[NN];
__device__ int    g_bsum[NSCAN_BLKS];
__device__ int    g_boff[NSCAN_BLKS];
__device__ float2 g_edge[EE];                        // (src as int bits, norm)
__device__ __half g_xsh[(size_t)NN * TW * CI_N];     // x transposed node-major, fp16, 38.4 MB
__device__ float  g_ax [(size_t)NN * TW * CI_N];     // aggregated x, fp32, 76.8 MB
__device__ float  g_M  [TW * 3 * CI_N * COUT];       // fused gcn_w @ conv_w
__device__ float  g_B  [TW * COUT];                  // fused bias

// ---- packed f32x2 helpers (Blackwell FFMA2) ----
__device__ __forceinline__ unsigned long long pk2(float lo, float hi) {
    unsigned long long r;
    asm("mov.b64 %0, {%1, %2};" : "=l"(r) : "f"(lo), "f"(hi));
    return r;
}
__device__ __forceinline__ void upk2(float& lo, float& hi, unsigned long long v) {
    asm("mov.b64 {%0, %1}, %2;" : "=f"(lo), "=f"(hi) : "l"(v));
}
__device__ __forceinline__ unsigned long long fma2(unsigned long long a,
                                                   unsigned long long b,
                                                   unsigned long long c) {
    unsigned long long d;
    asm("fma.rn.f32x2 %0, %1, %2, %3;" : "=l"(d) : "l"(a), "l"(b), "l"(c));
    return d;
}

// ---------- 0: zero accumulators ----------
__global__ void k_zero() {
    int i = blockIdx.x * blockDim.x + threadIdx.x;
    if (i < NN) { g_deg[i] = 0.f; g_cnt[i] = 0; }
}

// ---------- 1: weighted degree + edge-count histogram over dst ----------
__global__ void k_deg(const int* __restrict__ A, const float* __restrict__ ew) {
    int e = blockIdx.x * blockDim.x + threadIdx.x;
    if (e < EE) {
        int c = A[EE + e];
        atomicAdd(&g_deg[c], ew[e]);
        atomicAdd(&g_cnt[c], 1);
    }
}

// ---------- 2: dis = deg>0 ? rsqrt(deg) : 0 ----------
__global__ void k_dis() {
    int i = blockIdx.x * blockDim.x + threadIdx.x;
    if (i < NN) { float d = g_deg[i]; g_dis[i] = d > 0.f ? rsqrtf(d) : 0.f; }
}

// ---------- 3a: per-block exclusive scan of g_cnt ----------
__global__ void k_scan1() {
    __shared__ int wsum[33];
    const int tid = threadIdx.x, lane = tid & 31, wid = tid >> 5;
    const int i = blockIdx.x * SCAN_BLK + tid;
    int v = (i < NN) ? g_cnt[i] : 0;
    int incl = v;
    #pragma unroll
    for (int d = 1; d < 32; d <<= 1) {
        int t = __shfl_up_sync(0xffffffffu, incl, d);
        if (lane >= d) incl += t;
    }
    if (lane == 31) wsum[wid] = incl;
    __syncthreads();
    if (wid == 0) {
        int x  = wsum[lane];
        int ix = x;
        #pragma unroll
        for (int d = 1; d < 32; d <<= 1) {
            int t = __shfl_up_sync(0xffffffffu, ix, d);
            if (lane >= d) ix += t;
        }
        wsum[lane] = ix - x;
        if (lane == 31) wsum[32] = ix;
    }
    __syncthreads();
    if (i < NN) g_off[i] = wsum[wid] + incl - v;
    if (tid == 0) g_bsum[blockIdx.x] = wsum[32];
}

// ---------- 3b: exclusive scan of block totals ----------
__global__ void k_scan2() {
    const int lane = threadIdx.x & 31, wid = threadIdx.x >> 5;
    __shared__ int wtot[4];
    int v = (threadIdx.x < NSCAN_BLKS) ? g_bsum[threadIdx.x] : 0;
    int incl = v;
    #pragma unroll
    for (int d = 1; d < 32; d <<= 1) {
        int t = __shfl_up_sync(0xffffffffu, incl, d);
        if (lane >= d) incl += t;
    }
    if (lane == 31) wtot[wid] = incl;
    __syncthreads();
    int base = 0;
    for (int w = 0; w < wid; w++) base += wtot[w];
    if (threadIdx.x < NSCAN_BLKS) g_boff[threadIdx.x] = base + incl - v;
}

// ---------- 3c: add block offsets, init cursors ----------
__global__ void k_scan3() {
    int i = blockIdx.x * blockDim.x + threadIdx.x;
    if (i < NN) {
        int o = g_off[i] + g_boff[i / SCAN_BLK];
        g_off[i] = o;
        g_cur[i] = o;
    }
    if (i == 0) g_off[NN] = EE;
}

// ---------- 4: scatter edges into dst-sorted CSR (packed src+norm) ----------
__global__ void k_scatter(const int* __restrict__ A, const float* __restrict__ ew) {
    int e = blockIdx.x * blockDim.x + threadIdx.x;
    if (e < EE) {
        int r = A[e], c = A[EE + e];
        int idx = atomicAdd(&g_cur[c], 1);
        float nrm = g_dis[r] * ew[e] * g_dis[c];
        g_edge[idx] = make_float2(__int_as_float(r), nrm);
    }
}

// ---------- 5: transpose x -> node-major fp16 xs[n][t][ch] ----------
// one thread per (t,n): reads 16 contiguous floats, writes 16 halves (32B)
__global__ void k_xs(const float* __restrict__ x) {
    int gid = blockIdx.x * blockDim.x + threadIdx.x;
    if (gid >= TW * NN) return;
    int t = gid / NN, n = gid - t * NN;
    const float4* xp = (const float4*)(x + ((size_t)t * NN + n) * 16);
    float4 a = xp[0], b = xp[1], c = xp[2], d = xp[3];
    __align__(16) __half2 h[8];
    h[0] = __floats2half2_rn(a.x, a.y); h[1] = __floats2half2_rn(a.z, a.w);
    h[2] = __floats2half2_rn(b.x, b.y); h[3] = __floats2half2_rn(b.z, b.w);
    h[4] = __floats2half2_rn(c.x, c.y); h[5] = __floats2half2_rn(c.z, c.w);
    h[6] = __floats2half2_rn(d.x, d.y); h[7] = __floats2half2_rn(d.z, d.w);
    const uint4* src = (const uint4*)h;
    uint4* dst = (uint4*)(g_xsh + (size_t)n * 192 + t * 16);
    dst[0] = src[0];
    dst[1] = src[1];
}

// ---------- 6: fuse weights: M[t][k][ci][co] = sum_cm gw[t][ci][cm]*cw[co][cm][k] ----------
__global__ void k_fuse(const float* __restrict__ gw, const float* __restrict__ cw) {
    const int b = blockIdx.x;          // 0..35
    const int t = b / 3, k = b % 3;
    const int co = threadIdx.x, ci = threadIdx.y;
    float acc = 0.f;
    #pragma unroll
    for (int cm = 0; cm < CMID; cm++)
        acc = fmaf(gw[(t * CI_N + ci) * CMID + cm], cw[(co * CMID + cm) * 3 + k], acc);
    g_M[((t * 3 + k) * CI_N + ci) * COUT + co] = acc;
}

// ---------- 6b: fused bias B[w][co] ----------
__global__ void k_bias(const float* __restrict__ gb, const float* __restrict__ cw,
                       const float* __restrict__ cb) {
    const int co = threadIdx.x, w = threadIdx.y;
    float acc = cb[co];
    #pragma unroll
    for (int k = 0; k < 3; k++) {
        int t = w + k - 1;
        if (t >= 0 && t < TW)
            #pragma unroll
            for (int cm = 0; cm < CMID; cm++)
                acc = fmaf(gb[t * CMID + cm], cw[(co * CMID + cm) * 3 + k], acc);
    }
    g_B[w * COUT + co] = acc;
}

// ---------- 7: single-pass all-t aggregation over fp16 xs (warp per dst) ----------
__global__ void k_agg() {
    const int lane = threadIdx.x & 31, wid = threadIdx.x >> 5;
    const int dst = blockIdx.x * 8 + wid;              // 12500*8 == NN
    const int e0 = g_off[dst], e1 = g_off[dst + 1];
    float2 a0 = {0.f, 0.f}, a1 = {0.f, 0.f}, a2 = {0.f, 0.f};
    const unsigned int* xb = (const unsigned int*)g_xsh;   // half2 units, 96 per node
    #pragma unroll 2
    for (int e = e0; e < e1; e++) {
        float2 ed = g_edge[e];                         // warp-broadcast
        int   s = __float_as_int(ed.x);
        float w = ed.y;
        const unsigned int* p = xb + (size_t)s * 96 + lane;
        unsigned int u0 = p[0], u1 = p[32], u2 = p[64];
        float2 v0 = __half22float2(*(const __half2*)&u0);
        float2 v1 = __half22float2(*(const __half2*)&u1);
        float2 v2 = __half22float2(*(const __half2*)&u2);
        a0.x = fmaf(w, v0.x, a0.x); a0.y = fmaf(w, v0.y, a0.y);
        a1.x = fmaf(w, v1.x, a1.x); a1.y = fmaf(w, v1.y, a1.y);
        a2.x = fmaf(w, v2.x, a2.x); a2.y = fmaf(w, v2.y, a2.y);
    }
    float2* q = (float2*)(g_ax + (size_t)dst * 192) + lane;
    q[0] = a0; q[32] = a1; q[64] = a2;
}

// ---------- 8: output GEMM per w with packed f32x2 FMAs ----------
// block: 128 nodes x one w; thread: co = tid&31, grp = tid>>5 -> 16 nodes as 8 f32x2 accs
#define NPB 128
__global__ __launch_bounds__(256)
void k_out(float* __restrict__ out) {
    __shared__ __align__(16) float Xs[48][132];        // [r][node], row 132 keeps 16B align
    __shared__ float Gs[48 * 32];                      // [r][co]
    __shared__ float Bs[32];
    const int w   = blockIdx.y;
    const int n0  = blockIdx.x * NPB;
    const int tid = threadIdx.x;

    for (int idx = tid; idx < 48 * 32; idx += 256) {
        int r = idx >> 5, co = idx & 31;
        int k = r >> 4, ci = r & 15;
        int t = w - 1 + k;
        Gs[idx] = (t >= 0 && t < TW) ? g_M[((t * 3 + k) * CI_N + ci) * COUT + co] : 0.f;
    }
    if (tid < 32) Bs[tid] = g_B[w * COUT + tid];

    // fill Xs: 48 r-rows x 128 nodes, float4 granularity over r
    for (int q = tid; q < 12 * NPB; q += 256) {
        int nl = q / 12, j = q - nl * 12;              // j: float4 index within 48
        int fo = (w - 1) * 16 + 4 * j;                 // offset into node's 192 floats
        int n  = n0 + nl;
        float4 v = {0.f, 0.f, 0.f, 0.f};
        if (fo >= 0 && fo < 192 && n < NN)
            v = *(const float4*)(g_ax + (size_t)n * 192 + fo);
        Xs[4 * j + 0][nl] = v.x;
        Xs[4 * j + 1][nl] = v.y;
        Xs[4 * j + 2][nl] = v.z;
        Xs[4 * j + 3][nl] = v.w;
    }
    __syncthreads();

    const int co  = tid & 31;
    const int grp = tid >> 5;                          // 8 groups x 16 nodes
    unsigned long long acc[8];
    #pragma unroll
    for (int i = 0; i < 8; i++) acc[i] = 0ull;

    #pragma unroll
    for (int r = 0; r < 48; r++) {
        const ulonglong2* xp = (const ulonglong2*)&Xs[r][grp * 16];
        float gv = Gs[r * 32 + co];
        unsigned long long bb = pk2(gv, gv);
        ulonglong2 p0 = xp[0], p1 = xp[1], p2 = xp[2], p3 = xp[3];
        acc[0] = fma2(p0.x, bb, acc[0]); acc[1] = fma2(p0.y, bb, acc[1]);
        acc[2] = fma2(p1.x, bb, acc[2]); acc[3] = fma2(p1.y, bb, acc[3]);
        acc[4] = fma2(p2.x, bb, acc[4]); acc[5] = fma2(p2.y, bb, acc[5]);
        acc[6] = fma2(p3.x, bb, acc[6]); acc[7] = fma2(p3.y, bb, acc[7]);
    }

    const float bv = Bs[co];
    #pragma unroll
    for (int i = 0; i < 8; i++) {
        float f0, f1;
        upk2(f0, f1, acc[i]);
        int n = n0 + grp * 16 + 2 * i;
        if (n < NN) {
            float v0 = f0 + bv;
            v0 = v0 >= 0.f ? v0 : 0.01f * v0;
            out[(size_t)n * (TW * COUT) + w * COUT + co] = v0;
        }
        if (n + 1 < NN) {
            float v1 = f1 + bv;
            v1 = v1 >= 0.f ? v1 : 0.01f * v1;
            out[(size_t)(n + 1) * (TW * COUT) + w * COUT + co] = v1;
        }
    }
}

extern "C" void kernel_launch(void* const* d_in, const int* in_sizes, int n_in,
                              void* d_out, int out_size) {
    const float* x  = (const float*)d_in[0];   // [W,N,16]
    const int*   A  = (const int*)  d_in[1];   // [2,E]
    const float* ew = (const float*)d_in[2];   // [E]
    const float* gw = (const float*)d_in[3];   // [W,16,32]
    const float* gb = (const float*)d_in[4];   // [W,32]
    const float* cw = (const float*)d_in[5];   // [32,32,3]
    const float* cb = (const float*)d_in[6];   // [32]
    float* out = (float*)d_out;                // [N,W,32]

    k_zero   <<<(NN + 255) / 256, 256>>>();
    k_deg    <<<(EE + 255) / 256, 256>>>(A, ew);
    k_dis    <<<(NN + 255) / 256, 256>>>();
    k_scan1  <<<NSCAN_BLKS, SCAN_BLK>>>();
    k_scan2  <<<1, 128>>>();
    k_scan3  <<<NSCAN_BLKS, SCAN_BLK>>>();
    k_scatter<<<(EE + 255) / 256, 256>>>(A, ew);

    k_xs   <<<(TW * NN + 255) / 256, 256>>>(x);
    k_fuse <<<TW * 3, dim3(COUT, CI_N)>>>(gw, cw);
    k_bias <<<1, dim3(COUT, TW)>>>(gb, cw, cb);

    k_agg<<<NN / 8, 256>>>();
    k_out<<<dim3((NN + NPB - 1) / NPB, TW), 256>>>(out);
}